// round 11
// baseline (speedup 1.0000x reference)
#include <cuda_runtime.h>
#include <cuda.h>
#include <cuda_fp16.h>
#include <cstdint>
#include <math.h>

constexpr int BB = 2;
constexpr int CC = 512;
constexpr int NN = 4096;
constexpr int DD = 64;
constexpr int QK = 128;

// ---------------------------------------------------------------------------
// Scratch
// ---------------------------------------------------------------------------
__device__ __align__(1024) __half   g_qkh[(size_t)BB * NN * QK];  // [b][n][q|k]
__device__ __align__(1024) __half   g_vh [(size_t)BB * CC * NN];  // [b][c][j]
__device__ __align__(1024) __half   g_xTh[(size_t)BB * NN * CC];  // [b][n][c]
__device__ __align__(1024) __half   g_wrh[(size_t)CC * CC];       // Wv
__device__ __align__(1024) __half   g_wqkh[(size_t)QK * CC];      // Wq|Wk
__device__ __align__(1024) float    g_bqk[QK];
__device__ __align__(1024) __half   g_eh [(size_t)BB * NN * NN];  // exp(s - m)
__device__ __align__(1024) float    g_rs [(size_t)BB * NN];       // fp32 row sums
__device__ __align__(1024) unsigned g_rm [(size_t)BB * NN];       // encoded row max
__device__ __align__(1024) unsigned g_cnt[BB * 16];               // strip arrival counters

// ---------------------------------------------------------------------------
// Helpers
// ---------------------------------------------------------------------------
__device__ __forceinline__ uint32_t smem_to_u32(const void* p) {
    uint32_t a;
    asm("{ .reg .u64 t; cvta.to.shared.u64 t, %1; cvt.u32.u64 %0, t; }"
        : "=r"(a) : "l"(p));
    return a;
}
__device__ __forceinline__ unsigned fenc(float f) {
    unsigned u = __float_as_uint(f);
    return (u & 0x80000000u) ? ~u : (u | 0x80000000u);
}
__device__ __forceinline__ float fdec(unsigned e) {
    return (e & 0x80000000u) ? __uint_as_float(e ^ 0x80000000u)
                             : __uint_as_float(~e);
}

#define MBARRIER_INIT(addr, cnt) \
    asm volatile("mbarrier.init.shared.b64 [%0], %1;" \
        :: "r"((uint32_t)(addr)), "r"((uint32_t)(cnt)) : "memory")
#define MBARRIER_EXPECT_TX(addr, bytes) \
    asm volatile("mbarrier.arrive.expect_tx.shared.b64 _, [%0], %1;" \
        :: "r"((uint32_t)(addr)), "r"((uint32_t)(bytes)) : "memory")
#define MBARRIER_ARRIVE(addr) \
    asm volatile("mbarrier.arrive.shared.b64 _, [%0];" \
        :: "r"((uint32_t)(addr)) : "memory")
#define MBARRIER_WAIT_PARITY(addr, parity) do { \
    uint32_t _m = (uint32_t)(addr); uint32_t _p = (uint32_t)(parity); uint32_t _d; \
    asm volatile("{\n\t.reg .pred p;\n\t" \
        "mbarrier.try_wait.parity.shared.b64 p, [%1], %2;\n\t" \
        "selp.b32 %0, 1, 0, p;\n\t}" : "=r"(_d) : "r"(_m), "r"(_p) : "memory"); \
    if (!_d) { \
        asm volatile("{\n\t.reg .pred P1;\n\tWL_%=:\n\t" \
            "mbarrier.try_wait.parity.shared.b64 P1, [%0], %1, 0x989680;\n\t" \
            "@P1 bra.uni WD_%=;\n\tbra.uni WL_%=;\n\tWD_%=:\n\t}" \
            :: "r"(_m), "r"(_p) : "memory"); \
    } } while (0)

#define TMA_LOAD_3D(smem_addr, tmap, cx, cy, cz, mbar) \
    asm volatile( \
        "cp.async.bulk.tensor.3d.shared::cta.global.tile.mbarrier::complete_tx::bytes " \
        "[%0], [%1, {%2, %3, %4}], [%5];" \
        :: "r"((uint32_t)(smem_addr)), "l"(tmap), \
           "r"((int32_t)(cx)), "r"((int32_t)(cy)), "r"((int32_t)(cz)), \
           "r"((uint32_t)(mbar)) : "memory")

#define LDSM_X4(r0, r1, r2, r3, addr) \
    asm volatile("ldmatrix.sync.aligned.m8n8.x4.shared.b16 {%0,%1,%2,%3}, [%4];" \
        : "=r"(r0), "=r"(r1), "=r"(r2), "=r"(r3) : "r"(addr))

#define BAR_CONSUMERS() \
    asm volatile("bar.sync 1, 512;" ::: "memory")

__device__ __forceinline__ void mma_f16(float* d, const uint32_t* a, const uint32_t* b) {
    asm volatile(
        "mma.sync.aligned.m16n8k16.row.col.f32.f16.f16.f32 "
        "{%0,%1,%2,%3}, {%4,%5,%6,%7}, {%8,%9}, {%0,%1,%2,%3};"
        : "+f"(d[0]), "+f"(d[1]), "+f"(d[2]), "+f"(d[3])
        : "r"(a[0]), "r"(a[1]), "r"(a[2]), "r"(a[3]), "r"(b[0]), "r"(b[1]));
}

// ---------------------------------------------------------------------------
// Prep kernels
// ---------------------------------------------------------------------------
__global__ __launch_bounds__(256) void xT_half_kernel(const float* __restrict__ x)
{
    __shared__ float t[32][33];
    const int b  = blockIdx.z;
    const int n0 = blockIdx.x * 32, c0 = blockIdx.y * 32;
    const int tx = threadIdx.x & 31, ty = threadIdx.x >> 5;
    const float* xb = x + (size_t)b * CC * NN;
    #pragma unroll
    for (int i = 0; i < 32; i += 8)
        t[ty + i][tx] = xb[(size_t)(c0 + ty + i) * NN + n0 + tx];
    __syncthreads();
    __half* o = g_xTh + (size_t)b * NN * CC;
    #pragma unroll
    for (int i = 0; i < 32; i += 8)
        o[(size_t)(n0 + ty + i) * CC + c0 + tx] = __float2half_rn(t[tx][ty + i]);
}

// Wv -> fp16, Wq|Wk -> fp16, biases, zero rs, init rm, zero strip counters
__global__ __launch_bounds__(256) void prep_kernel(
    const float* __restrict__ Wv,
    const float* __restrict__ Wq, const float* __restrict__ bq,
    const float* __restrict__ Wk, const float* __restrict__ bk)
{
    int i = blockIdx.x * 256 + threadIdx.x;     // over CC*CC = 262144
    g_wrh[i] = __float2half_rn(Wv[i]);
    if (i < QK * CC) {
        int r = i >> 9, c = i & 511;
        g_wqkh[i] = __float2half_rn(r < DD ? Wq[(size_t)r * CC + c]
                                           : Wk[(size_t)(r - DD) * CC + c]);
    }
    if (i < QK) g_bqk[i] = (i < DD) ? bq[i] : bk[i - DD];
    if (i < BB * NN) { g_rs[i] = 0.0f; g_rm[i] = 0x007FFFFFu; }
    if (i < BB * 16) g_cnt[i] = 0u;
}

// ---------------------------------------------------------------------------
// fp16 GEMM, templated on MT (warp m-tiles): BM = MT*64, BN = 128, BK = 64.
// mode 0: half out = C + bias[row]                        (v-proj)
// mode 2: fused scores: atomicMax rowmax -> strip barrier -> exp/store/rowsum
// mode 3: half out = C + bias[col]                        (qk-proj)
// ---------------------------------------------------------------------------
constexpr int BN = 128;
constexpr int NSTAGE = 3;
constexpr int B16_BY = BN * 128;                  // 16 KB

template<int MT>
__global__ __launch_bounds__(544)
void gemm16_kernel(const __grid_constant__ CUtensorMap tma_a,
                   const __grid_constant__ CUtensorMap tma_b,
                   int k_total, int mode, int a_batched, int b_batched,
                   int a_koff, int b_koff,
                   const float* __restrict__ aux,
                   float* __restrict__ rs, unsigned* __restrict__ rm,
                   unsigned* __restrict__ cnt,
                   void* __restrict__ outp, size_t out_bstride, int out_rstride)
{
    constexpr int BM_T = MT * 64;
    constexpr int A_BY = BM_T * 128;
    constexpr int STG  = A_BY + B16_BY;

    __shared__ __align__(8) uint64_t s_bar[2 * NSTAGE];
    extern __shared__ char dsm[];
    const uint32_t dbase = (smem_to_u32(dsm) + 1023) & ~1023u;
    const uint32_t sbar  = smem_to_u32(s_bar);

    const int tid = threadIdx.x, wid = tid >> 5, lid = tid & 31;
    const int mBase = blockIdx.y * BM_T;
    const int nBase = blockIdx.x * BN;
    const int b     = blockIdx.z;
    const int nchunk = k_total / 64;

    if (tid == 0) {
        #pragma unroll
        for (int s = 0; s < NSTAGE; s++) {
            MBARRIER_INIT(sbar + s * 16, 1);
            MBARRIER_INIT(sbar + s * 16 + 8, 16);
        }
    }
    __syncthreads();

    if (tid == 512) {
        const int az = a_batched ? b : 0;
        const int bz = b_batched ? b : 0;
        int ph = 1, st = 0;
        for (int c = 0; c < nchunk; c++) {
            MBARRIER_WAIT_PARITY(sbar + st * 16 + 8, ph);
            MBARRIER_EXPECT_TX(sbar + st * 16, STG);
            TMA_LOAD_3D(dbase + st * STG,        &tma_a, a_koff + c * 64, mBase, az, sbar + st * 16);
            TMA_LOAD_3D(dbase + st * STG + A_BY, &tma_b, b_koff + c * 64, nBase, bz, sbar + st * 16);
            if (++st == NSTAGE) { st = 0; ph ^= 1; }
        }
    }

    if (wid < 16) {
        const int wm = wid & 3, wn = wid >> 2;
        const int mWarp = wm * (MT * 16), nWarp = wn * 32;
        const int laneA = lid & 15;
        const int hAu   = (lid >> 4) & 1;
        const int laneB = (lid & 7) + ((lid & 16) ? 8 : 0);
        const int hBu   = (lid >> 3) & 1;
        const int xor7  = lid & 7;

        float cacc[MT][4][4] = {};

        int ph = 0, st = 0;
        for (int c = 0; c < nchunk; c++) {
            MBARRIER_WAIT_PARITY(sbar + st * 16, ph);
            const uint32_t Ab = dbase + st * STG;
            const uint32_t Bb = Ab + A_BY;
            const uint32_t aRowAddr = Ab + (mWarp + laneA) * 128;
            const uint32_t bRowAddr = Bb + (nWarp + laneB) * 128;

            #pragma unroll
            for (int ks = 0; ks < 4; ks++) {
                uint32_t af[MT][4];
                uint32_t bf[4][2];
                const uint32_t cA = (uint32_t)(((2 * ks + hAu) ^ xor7) << 4);
                const uint32_t cB = (uint32_t)(((2 * ks + hBu) ^ xor7) << 4);
                #pragma unroll
                for (int mt = 0; mt < MT; mt++)
                    LDSM_X4(af[mt][0], af[mt][1], af[mt][2], af[mt][3],
                            aRowAddr + mt * (16 * 128) + cA);
                #pragma unroll
                for (int p = 0; p < 2; p++) {
                    uint32_t r0, r1, r2, r3;
                    LDSM_X4(r0, r1, r2, r3, bRowAddr + p * (16 * 128) + cB);
                    bf[2*p][0] = r0; bf[2*p][1] = r1;
                    bf[2*p+1][0] = r2; bf[2*p+1][1] = r3;
                }
                #pragma unroll
                for (int mt = 0; mt < MT; mt++)
                    #pragma unroll
                    for (int nt = 0; nt < 4; nt++)
                        mma_f16(cacc[mt][nt], af[mt], bf[nt]);
            }
            if (lid == 0) MBARRIER_ARRIVE(sbar + st * 16 + 8);
            if (++st == NSTAGE) { st = 0; ph ^= 1; }
        }

        // ---- epilogue ----
        const int g = lid >> 2, t4 = lid & 3;
        float* rs_b = rs + (size_t)b * NN;
        unsigned* rm_b = rm + (size_t)b * NN;

        if (mode == 2) {
            // Phase A: local row maxes -> global atomicMax
            #pragma unroll
            for (int mt = 0; mt < MT; mt++) {
                const int r0 = mBase + mWarp + mt * 16 + g;
                const int r1 = r0 + 8;
                float m0 = -1e30f, m1 = -1e30f;
                #pragma unroll
                for (int nt = 0; nt < 4; nt++) {
                    m0 = fmaxf(m0, fmaxf(cacc[mt][nt][0], cacc[mt][nt][1]));
                    m1 = fmaxf(m1, fmaxf(cacc[mt][nt][2], cacc[mt][nt][3]));
                }
                m0 = fmaxf(m0, __shfl_xor_sync(~0u, m0, 1));
                m0 = fmaxf(m0, __shfl_xor_sync(~0u, m0, 2));
                m1 = fmaxf(m1, __shfl_xor_sync(~0u, m1, 1));
                m1 = fmaxf(m1, __shfl_xor_sync(~0u, m1, 2));
                if (t4 == 0) {
                    atomicMax(&rm_b[r0], fenc(m0));
                    atomicMax(&rm_b[r1], fenc(m1));
                }
            }
            __threadfence();
            BAR_CONSUMERS();
            // strip barrier: all gridDim.x j-CTAs of this (i-strip, b) must arrive
            if (tid == 0) {
                unsigned* c = &cnt[blockIdx.z * gridDim.y + blockIdx.y];
                atomicAdd(c, 1u);
                while (atomicAdd(c, 0u) < gridDim.x) {}
            }
            BAR_CONSUMERS();

            // Phase B: exp(C - rowmax), store fp16, fp32 rowsums
            __half* ob = (__half*)outp + (size_t)b * out_bstride;
            #pragma unroll
            for (int mt = 0; mt < MT; mt++) {
                const int r0 = mBase + mWarp + mt * 16 + g;
                const int r1 = r0 + 8;
                const float m0 = fdec(atomicOr(&rm_b[r0], 0u));
                const float m1 = fdec(atomicOr(&rm_b[r1], 0u));
                float s0 = 0.f, s1 = 0.f;
                #pragma unroll
                for (int nt = 0; nt < 4; nt++) {
                    const int col = nBase + nWarp + nt * 8 + t4 * 2;
                    const float v00 = __expf(cacc[mt][nt][0] - m0);
                    const float v01 = __expf(cacc[mt][nt][1] - m0);
                    const float v10 = __expf(cacc[mt][nt][2] - m1);
                    const float v11 = __expf(cacc[mt][nt][3] - m1);
                    s0 += v00 + v01; s1 += v10 + v11;
                    *(__half2*)&ob[(size_t)r0 * out_rstride + col] = __floats2half2_rn(v00, v01);
                    *(__half2*)&ob[(size_t)r1 * out_rstride + col] = __floats2half2_rn(v10, v11);
                }
                s0 += __shfl_xor_sync(0xFFFFFFFFu, s0, 1);
                s0 += __shfl_xor_sync(0xFFFFFFFFu, s0, 2);
                s1 += __shfl_xor_sync(0xFFFFFFFFu, s1, 1);
                s1 += __shfl_xor_sync(0xFFFFFFFFu, s1, 2);
                if (t4 == 0) {
                    atomicAdd(&rs_b[r0], s0);
                    atomicAdd(&rs_b[r1], s1);
                }
            }
        } else {
            // mode 0 / mode 3
            #pragma unroll
            for (int mt = 0; mt < MT; mt++) {
                const int r0 = mBase + mWarp + mt * 16 + g;
                const int r1 = r0 + 8;
                float bias0 = 0.f, bias1 = 0.f;
                if (mode == 0) { bias0 = aux[r0]; bias1 = aux[r1]; }
                __half* ob = (__half*)outp + (size_t)b * out_bstride;
                #pragma unroll
                for (int nt = 0; nt < 4; nt++) {
                    const int col = nBase + nWarp + nt * 8 + t4 * 2;
                    float v00 = cacc[mt][nt][0], v01 = cacc[mt][nt][1];
                    float v10 = cacc[mt][nt][2], v11 = cacc[mt][nt][3];
                    if (mode == 3) {
                        const float bc0 = aux[col], bc1 = aux[col + 1];
                        v00 += bc0; v01 += bc1; v10 += bc0; v11 += bc1;
                    } else {
                        v00 += bias0; v01 += bias0; v10 += bias1; v11 += bias1;
                    }
                    *(__half2*)&ob[(size_t)r0 * out_rstride + col] = __floats2half2_rn(v00, v01);
                    *(__half2*)&ob[(size_t)r1 * out_rstride + col] = __floats2half2_rn(v10, v11);
                }
            }
        }
    }
}

// ---------------------------------------------------------------------------
// fp16 AV GEMM with BK=128: out[c][i] = gamma*(sum_j v[c][j]*e[i][j])/rs[i] + x
// Tile 256(c) x 128(i) x 128(j), 2 stages x 96 KB.
// ---------------------------------------------------------------------------
constexpr int AV_A_ST = 256 * 256;                // 64 KB
constexpr int AV_B_ST = 128 * 256;                // 32 KB
constexpr int AV_STG  = AV_A_ST + AV_B_ST;        // 96 KB
constexpr int AV_DSMEM = 2 * AV_STG + 1024;

__global__ __launch_bounds__(544)
void av16_kernel(const __grid_constant__ CUtensorMap tma_v,
                 const __grid_constant__ CUtensorMap tma_e,
                 const float* __restrict__ x,
                 const float* __restrict__ rs,
                 const float* __restrict__ gamma,
                 float* __restrict__ outp)
{
    __shared__ __align__(8) uint64_t s_bar[4];
    extern __shared__ char dsm[];
    const uint32_t dbase = (smem_to_u32(dsm) + 1023) & ~1023u;
    const uint32_t sbar  = smem_to_u32(s_bar);

    const int tid = threadIdx.x, wid = tid >> 5, lid = tid & 31;
    const int mBase = blockIdx.x * 256;     // c
    const int nBase = blockIdx.y * 128;     // i
    const int b     = blockIdx.z;
    const int nchunk = NN / 128;            // 32

    if (tid == 0) {
        #pragma unroll
        for (int s = 0; s < 2; s++) {
            MBARRIER_INIT(sbar + s * 16, 1);
            MBARRIER_INIT(sbar + s * 16 + 8, 16);
        }
    }
    __syncthreads();

    if (tid == 512) {
        int ph = 1, st = 0;
        for (int c = 0; c < nchunk; c++) {
            MBARRIER_WAIT_PARITY(sbar + st * 16 + 8, ph);
            MBARRIER_EXPECT_TX(sbar + st * 16, AV_STG);
            const uint32_t SB = dbase + st * AV_STG;
            TMA_LOAD_3D(SB,                   &tma_v, c * 128,      mBase, b, sbar + st * 16);
            TMA_LOAD_3D(SB + 32768,           &tma_v, c * 128 + 64, mBase, b, sbar + st * 16);
            TMA_LOAD_3D(SB + AV_A_ST,         &tma_e, c * 128,      nBase, b, sbar + st * 16);
            TMA_LOAD_3D(SB + AV_A_ST + 16384, &tma_e, c * 128 + 64, nBase, b, sbar + st * 16);
            if (++st == 2) { st = 0; ph ^= 1; }
        }
    }

    if (wid < 16) {
        const int wm = wid & 3, wn = wid >> 2;
        const int mWarp = wm * 64, nWarp = wn * 32;
        const int laneA = lid & 15;
        const int hAu   = (lid >> 4) & 1;
        const int laneB = (lid & 7) + ((lid & 16) ? 8 : 0);
        const int hBu   = (lid >> 3) & 1;
        const int xor7  = lid & 7;

        float cacc[4][4][4] = {};

        int ph = 0, st = 0;
        for (int c = 0; c < nchunk; c++) {
            MBARRIER_WAIT_PARITY(sbar + st * 16, ph);
            const uint32_t Ab = dbase + st * AV_STG;
            const uint32_t Bb = Ab + AV_A_ST;
            const uint32_t aRowAddr = Ab + (mWarp + laneA) * 128;
            const uint32_t bRowAddr = Bb + (nWarp + laneB) * 128;

            #pragma unroll
            for (int kt = 0; kt < 2; kt++) {
                #pragma unroll
                for (int ks = 0; ks < 4; ks++) {
                    uint32_t af[4][4];
                    uint32_t bf[4][2];
                    const uint32_t cA = (uint32_t)(((2 * ks + hAu) ^ xor7) << 4);
                    const uint32_t cB = (uint32_t)(((2 * ks + hBu) ^ xor7) << 4);
                    #pragma unroll
                    for (int mt = 0; mt < 4; mt++)
                        LDSM_X4(af[mt][0], af[mt][1], af[mt][2], af[mt][3],
                                aRowAddr + kt * 32768 + mt * (16 * 128) + cA);
                    #pragma unroll
                    for (int p = 0; p < 2; p++) {
                        uint32_t r0, r1, r2, r3;
                        LDSM_X4(r0, r1, r2, r3, bRowAddr + kt * 16384 + p * (16 * 128) + cB);
                        bf[2*p][0] = r0; bf[2*p][1] = r1;
                        bf[2*p+1][0] = r2; bf[2*p+1][1] = r3;
                    }
                    #pragma unroll
                    for (int mt = 0; mt < 4; mt++)
                        #pragma unroll
                        for (int nt = 0; nt < 4; nt++)
                            mma_f16(cacc[mt][nt], af[mt], bf[nt]);
                }
            }
            if (lid == 0) MBARRIER_ARRIVE(sbar + st * 16 + 8);
            if (++st == 2) { st = 0; ph ^= 1; }
        }

        const int g = lid >> 2, t4 = lid & 3;
        const float gm = gamma[0];
        const float* rs_b = rs + (size_t)b * NN;
        const float* xb = x + (size_t)b * CC * NN;
        float* ob = outp + (size_t)b * CC * NN;

        #pragma unroll
        for (int mt = 0; mt < 4; mt++) {
            const int r0 = mBase + mWarp + mt * 16 + g;
            const int r1 = r0 + 8;
            #pragma unroll
            for (int nt = 0; nt < 4; nt++) {
                const int col = nBase + nWarp + nt * 8 + t4 * 2;
                const float i0 = __fdividef(1.0f, rs_b[col]);
                const float i1 = __fdividef(1.0f, rs_b[col + 1]);
                const float2 x0 = *(const float2*)&xb[(size_t)r0 * NN + col];
                const float2 x1 = *(const float2*)&xb[(size_t)r1 * NN + col];
                *(float2*)&ob[(size_t)r0 * NN + col] =
                    make_float2(gm * cacc[mt][nt][0] * i0 + x0.x,
                                gm * cacc[mt][nt][1] * i1 + x0.y);
                *(float2*)&ob[(size_t)r1 * NN + col] =
                    make_float2(gm * cacc[mt][nt][2] * i0 + x1.x,
                                gm * cacc[mt][nt][3] * i1 + x1.y);
            }
        }
    }
}

// ---------------------------------------------------------------------------
// Host side
// ---------------------------------------------------------------------------
typedef CUresult (*EncodeFn)(CUtensorMap*, CUtensorMapDataType, cuuint32_t, void*,
                             const cuuint64_t*, const cuuint64_t*, const cuuint32_t*,
                             const cuuint32_t*, CUtensorMapInterleave, CUtensorMapSwizzle,
                             CUtensorMapL2promotion, CUtensorMapFloatOOBfill);

static void build_tm(EncodeFn enc, CUtensorMap* tm, void* ptr,
                     uint64_t d0, uint64_t d1, uint64_t d2,
                     uint64_t s1b, uint64_t s2b, uint32_t b0, uint32_t b1)
{
    cuuint64_t dims[3] = {d0, d1, d2};
    cuuint64_t str[2]  = {s1b, s2b};
    cuuint32_t box[3]  = {b0, b1, 1};
    cuuint32_t es[3]   = {1, 1, 1};
    enc(tm, CU_TENSOR_MAP_DATA_TYPE_FLOAT16, 3, ptr, dims, str, box, es,
        CU_TENSOR_MAP_INTERLEAVE_NONE, CU_TENSOR_MAP_SWIZZLE_128B,
        CU_TENSOR_MAP_L2_PROMOTION_L2_128B, CU_TENSOR_MAP_FLOAT_OOB_FILL_NONE);
}

extern "C" void kernel_launch(void* const* d_in, const int* in_sizes, int n_in,
                              void* d_out, int out_size)
{
    (void)in_sizes; (void)n_in; (void)out_size;
    const float* x     = (const float*)d_in[0];
    const float* Wq    = (const float*)d_in[1];
    const float* bq    = (const float*)d_in[2];
    const float* Wk    = (const float*)d_in[3];
    const float* bk    = (const float*)d_in[4];
    const float* Wv    = (const float*)d_in[5];
    const float* bv    = (const float*)d_in[6];
    const float* gamma = (const float*)d_in[7];
    float* out = (float*)d_out;

    EncodeFn enc = nullptr;
    cudaDriverEntryPointQueryResult qr;
    cudaGetDriverEntryPointByVersion("cuTensorMapEncodeTiled", (void**)&enc, 12000,
                                     cudaEnableDefault, &qr);

    void *pqk, *pvh, *peh, *pxT, *pwr, *pwqk, *pbqk, *prs, *prm, *pcnt;
    cudaGetSymbolAddress(&pqk,  g_qkh);
    cudaGetSymbolAddress(&pvh,  g_vh);
    cudaGetSymbolAddress(&peh,  g_eh);
    cudaGetSymbolAddress(&pxT,  g_xTh);
    cudaGetSymbolAddress(&pwr,  g_wrh);
    cudaGetSymbolAddress(&pwqk, g_wqkh);
    cudaGetSymbolAddress(&pbqk, g_bqk);
    cudaGetSymbolAddress(&prs,  g_rs);
    cudaGetSymbolAddress(&prm,  g_rm);
    cudaGetSymbolAddress(&pcnt, g_cnt);

    CUtensorMap tmXT_A64, tmXT_B, tmWQK, tmWV, tmQKa, tmQKb, tmVh256, tmEh128;
    build_tm(enc, &tmXT_A64, pxT, CC, NN, BB, (uint64_t)CC * 2, (uint64_t)NN * CC * 2, 64, 64);
    build_tm(enc, &tmXT_B,   pxT, CC, NN, BB, (uint64_t)CC * 2, (uint64_t)NN * CC * 2, 64, 128);
    build_tm(enc, &tmWQK, pwqk, CC, QK, 1, (uint64_t)CC * 2, (uint64_t)QK * CC * 2, 64, 128);
    build_tm(enc, &tmWV,  pwr,  CC, CC, 1, (uint64_t)CC * 2, (uint64_t)CC * CC * 2, 64, 256);
    build_tm(enc, &tmQKa, pqk, QK, NN, BB, (uint64_t)QK * 2, (uint64_t)NN * QK * 2, 64, 256);
    build_tm(enc, &tmQKb, pqk, QK, NN, BB, (uint64_t)QK * 2, (uint64_t)NN * QK * 2, 64, 128);
    build_tm(enc, &tmVh256, pvh, NN, CC, BB, (uint64_t)NN * 2, (uint64_t)CC * NN * 2, 64, 256);
    build_tm(enc, &tmEh128, peh, NN, NN, BB, (uint64_t)NN * 2, (uint64_t)NN * NN * 2, 64, 128);

    constexpr int DS1 = NSTAGE * (64 * 128 + B16_BY) + 1024;    // MT=1
    constexpr int DS4 = NSTAGE * (256 * 128 + B16_BY) + 1024;   // MT=4
    cudaFuncSetAttribute(gemm16_kernel<1>, cudaFuncAttributeMaxDynamicSharedMemorySize, DS1);
    cudaFuncSetAttribute(gemm16_kernel<4>, cudaFuncAttributeMaxDynamicSharedMemorySize, DS4);
    cudaFuncSetAttribute(av16_kernel, cudaFuncAttributeMaxDynamicSharedMemorySize, AV_DSMEM);

    float* frs = (float*)prs;
    unsigned* frm = (unsigned*)prm;
    unsigned* fcnt = (unsigned*)pcnt;

    // 1. prep
    xT_half_kernel<<<dim3(NN / 32, CC / 32, BB), 256>>>(x);
    prep_kernel<<<(CC * CC) / 256, 256>>>(Wv, Wq, bq, Wk, bk);
    // 2. qk projection (MT=1, BM=64): 128 CTAs, K=512
    gemm16_kernel<1><<<dim3(QK / BN, NN / 64, BB), 544, DS1>>>(
        tmXT_A64, tmWQK, CC, 3, 1, 0, 0, 0, (const float*)pbqk, frs, frm, fcnt,
        pqk, (size_t)NN * QK, QK);
    // 3. v projection (MT=4): g_vh[c][n] = wr·xT^T + bv[c], K=512
    gemm16_kernel<4><<<dim3(NN / BN, CC / 256, BB), 544, DS4>>>(
        tmWV, tmXT_B, CC, 0, 0, 1, 0, 0, bv, frs, frm, fcnt,
        pvh, (size_t)CC * NN, NN);
    // 4. fused scores: max + strip-barrier + exp + rowsum, ONE QK^T pass, K=64
    gemm16_kernel<4><<<dim3(NN / BN, NN / 256, BB), 544, DS4>>>(
        tmQKa, tmQKb, DD, 2, 1, 1, 0, DD, nullptr, frs, frm, fcnt,
        peh, (size_t)NN * NN, NN);
    // 5. AV (fp16, BK=128): out = gamma*(v·e^T)/rs + x, K=4096
    av16_kernel<<<dim3(CC / 256, NN / 128, BB), 544, AV_DSMEM>>>(
        tmVh256, tmEh128, x, frs, gamma, out);
}

// round 12
// speedup vs baseline: 1.3131x; 1.3131x over previous
#include <cuda_runtime.h>
#include <cuda.h>
#include <cuda_fp16.h>
#include <cuda_bf16.h>
#include <cstdint>
#include <math.h>

constexpr int BB = 2;
constexpr int CC = 512;
constexpr int NN = 4096;
constexpr int DD = 64;
constexpr int QK = 128;

// ---------------------------------------------------------------------------
// Scratch
// ---------------------------------------------------------------------------
__device__ __align__(1024) __half         g_qkh[(size_t)BB * NN * QK]; // fp16 q|k
__device__ __align__(1024) __nv_bfloat16  g_vb [(size_t)BB * CC * NN]; // bf16 v
__device__ __align__(1024) __half         g_xTh[(size_t)BB * NN * CC]; // fp16 xT
__device__ __align__(1024) __half         g_wrh[(size_t)CC * CC];      // fp16 Wv
__device__ __align__(1024) __half         g_wqkh[(size_t)QK * CC];     // fp16 Wq|Wk
__device__ __align__(1024) float          g_bqk[QK];
__device__ __align__(1024) __nv_bfloat16  g_eb [(size_t)BB * NN * NN]; // bf16 exp(s)
__device__ __align__(1024) float          g_rs [(size_t)BB * NN];      // fp32 row sums

// ---------------------------------------------------------------------------
// Helpers
// ---------------------------------------------------------------------------
__device__ __forceinline__ uint32_t smem_to_u32(const void* p) {
    uint32_t a;
    asm("{ .reg .u64 t; cvta.to.shared.u64 t, %1; cvt.u32.u64 %0, t; }"
        : "=r"(a) : "l"(p));
    return a;
}

#define MBARRIER_INIT(addr, cnt) \
    asm volatile("mbarrier.init.shared.b64 [%0], %1;" \
        :: "r"((uint32_t)(addr)), "r"((uint32_t)(cnt)) : "memory")
#define MBARRIER_EXPECT_TX(addr, bytes) \
    asm volatile("mbarrier.arrive.expect_tx.shared.b64 _, [%0], %1;" \
        :: "r"((uint32_t)(addr)), "r"((uint32_t)(bytes)) : "memory")
#define MBARRIER_ARRIVE(addr) \
    asm volatile("mbarrier.arrive.shared.b64 _, [%0];" \
        :: "r"((uint32_t)(addr)) : "memory")
#define MBARRIER_WAIT_PARITY(addr, parity) do { \
    uint32_t _m = (uint32_t)(addr); uint32_t _p = (uint32_t)(parity); uint32_t _d; \
    asm volatile("{\n\t.reg .pred p;\n\t" \
        "mbarrier.try_wait.parity.shared.b64 p, [%1], %2;\n\t" \
        "selp.b32 %0, 1, 0, p;\n\t}" : "=r"(_d) : "r"(_m), "r"(_p) : "memory"); \
    if (!_d) { \
        asm volatile("{\n\t.reg .pred P1;\n\tWL_%=:\n\t" \
            "mbarrier.try_wait.parity.shared.b64 P1, [%0], %1, 0x989680;\n\t" \
            "@P1 bra.uni WD_%=;\n\tbra.uni WL_%=;\n\tWD_%=:\n\t}" \
            :: "r"(_m), "r"(_p) : "memory"); \
    } } while (0)

#define TMA_LOAD_3D(smem_addr, tmap, cx, cy, cz, mbar) \
    asm volatile( \
        "cp.async.bulk.tensor.3d.shared::cta.global.tile.mbarrier::complete_tx::bytes " \
        "[%0], [%1, {%2, %3, %4}], [%5];" \
        :: "r"((uint32_t)(smem_addr)), "l"(tmap), \
           "r"((int32_t)(cx)), "r"((int32_t)(cy)), "r"((int32_t)(cz)), \
           "r"((uint32_t)(mbar)) : "memory")

#define LDSM_X4(r0, r1, r2, r3, addr) \
    asm volatile("ldmatrix.sync.aligned.m8n8.x4.shared.b16 {%0,%1,%2,%3}, [%4];" \
        : "=r"(r0), "=r"(r1), "=r"(r2), "=r"(r3) : "r"(addr))

__device__ __forceinline__ void mma_f16(float* d, const uint32_t* a, const uint32_t* b) {
    asm volatile(
        "mma.sync.aligned.m16n8k16.row.col.f32.f16.f16.f32 "
        "{%0,%1,%2,%3}, {%4,%5,%6,%7}, {%8,%9}, {%0,%1,%2,%3};"
        : "+f"(d[0]), "+f"(d[1]), "+f"(d[2]), "+f"(d[3])
        : "r"(a[0]), "r"(a[1]), "r"(a[2]), "r"(a[3]), "r"(b[0]), "r"(b[1]));
}
__device__ __forceinline__ void mma_bf16(float* d, const uint32_t* a, const uint32_t* b) {
    asm volatile(
        "mma.sync.aligned.m16n8k16.row.col.f32.bf16.bf16.f32 "
        "{%0,%1,%2,%3}, {%4,%5,%6,%7}, {%8,%9}, {%0,%1,%2,%3};"
        : "+f"(d[0]), "+f"(d[1]), "+f"(d[2]), "+f"(d[3])
        : "r"(a[0]), "r"(a[1]), "r"(a[2]), "r"(a[3]), "r"(b[0]), "r"(b[1]));
}

// ---------------------------------------------------------------------------
// Prep kernels
// ---------------------------------------------------------------------------
__global__ __launch_bounds__(256) void xT_half_kernel(const float* __restrict__ x)
{
    __shared__ float t[32][33];
    const int b  = blockIdx.z;
    const int n0 = blockIdx.x * 32, c0 = blockIdx.y * 32;
    const int tx = threadIdx.x & 31, ty = threadIdx.x >> 5;
    const float* xb = x + (size_t)b * CC * NN;
    #pragma unroll
    for (int i = 0; i < 32; i += 8)
        t[ty + i][tx] = xb[(size_t)(c0 + ty + i) * NN + n0 + tx];
    __syncthreads();
    __half* o = g_xTh + (size_t)b * NN * CC;
    #pragma unroll
    for (int i = 0; i < 32; i += 8)
        o[(size_t)(n0 + ty + i) * CC + c0 + tx] = __float2half_rn(t[tx][ty + i]);
}

// Wv -> fp16, Wq|Wk -> fp16, biases, zero rs
__global__ __launch_bounds__(256) void prep_kernel(
    const float* __restrict__ Wv,
    const float* __restrict__ Wq, const float* __restrict__ bq,
    const float* __restrict__ Wk, const float* __restrict__ bk)
{
    int i = blockIdx.x * 256 + threadIdx.x;     // over CC*CC
    g_wrh[i] = __float2half_rn(Wv[i]);
    if (i < QK * CC) {
        int r = i >> 9, c = i & 511;
        g_wqkh[i] = __float2half_rn(r < DD ? Wq[(size_t)r * CC + c]
                                           : Wk[(size_t)(r - DD) * CC + c]);
    }
    if (i < QK) g_bqk[i] = (i < DD) ? bq[i] : bk[i - DD];
    if (i < BB * NN) g_rs[i] = 0.0f;
}

// ---------------------------------------------------------------------------
// fp16-input GEMM, templated on MT: BM = MT*64, BN = 128, BK = 64.
// mode 0: bf16 out = C + bias[row]                       (v-proj)
// mode 2: bf16 out = exp(C); fp32 rowsum atomics         (scores, no max!)
// mode 3: fp16 out = C + bias[col]                       (qk-proj)
// ---------------------------------------------------------------------------
constexpr int BN = 128;
constexpr int NSTAGE = 3;
constexpr int B16_BY = BN * 128;                  // 16 KB

template<int MT>
__global__ __launch_bounds__(544)
void gemm16_kernel(const __grid_constant__ CUtensorMap tma_a,
                   const __grid_constant__ CUtensorMap tma_b,
                   int k_total, int mode, int a_batched, int b_batched,
                   int a_koff, int b_koff,
                   const float* __restrict__ aux,
                   float* __restrict__ rs,
                   void* __restrict__ outp, size_t out_bstride, int out_rstride)
{
    constexpr int BM_T = MT * 64;
    constexpr int A_BY = BM_T * 128;
    constexpr int STG  = A_BY + B16_BY;

    __shared__ __align__(8) uint64_t s_bar[2 * NSTAGE];
    extern __shared__ char dsm[];
    const uint32_t dbase = (smem_to_u32(dsm) + 1023) & ~1023u;
    const uint32_t sbar  = smem_to_u32(s_bar);

    const int tid = threadIdx.x, wid = tid >> 5, lid = tid & 31;
    const int mBase = blockIdx.y * BM_T;
    const int nBase = blockIdx.x * BN;
    const int b     = blockIdx.z;
    const int nchunk = k_total / 64;

    if (tid == 0) {
        #pragma unroll
        for (int s = 0; s < NSTAGE; s++) {
            MBARRIER_INIT(sbar + s * 16, 1);
            MBARRIER_INIT(sbar + s * 16 + 8, 16);
        }
    }
    __syncthreads();

    if (tid == 512) {
        const int az = a_batched ? b : 0;
        const int bz = b_batched ? b : 0;
        int ph = 1, st = 0;
        for (int c = 0; c < nchunk; c++) {
            MBARRIER_WAIT_PARITY(sbar + st * 16 + 8, ph);
            MBARRIER_EXPECT_TX(sbar + st * 16, STG);
            TMA_LOAD_3D(dbase + st * STG,        &tma_a, a_koff + c * 64, mBase, az, sbar + st * 16);
            TMA_LOAD_3D(dbase + st * STG + A_BY, &tma_b, b_koff + c * 64, nBase, bz, sbar + st * 16);
            if (++st == NSTAGE) { st = 0; ph ^= 1; }
        }
    }

    if (wid < 16) {
        const int wm = wid & 3, wn = wid >> 2;
        const int mWarp = wm * (MT * 16), nWarp = wn * 32;
        const int laneA = lid & 15;
        const int hAu   = (lid >> 4) & 1;
        const int laneB = (lid & 7) + ((lid & 16) ? 8 : 0);
        const int hBu   = (lid >> 3) & 1;
        const int xor7  = lid & 7;

        float cacc[MT][4][4] = {};

        int ph = 0, st = 0;
        for (int c = 0; c < nchunk; c++) {
            MBARRIER_WAIT_PARITY(sbar + st * 16, ph);
            const uint32_t Ab = dbase + st * STG;
            const uint32_t Bb = Ab + A_BY;
            const uint32_t aRowAddr = Ab + (mWarp + laneA) * 128;
            const uint32_t bRowAddr = Bb + (nWarp + laneB) * 128;

            #pragma unroll
            for (int ks = 0; ks < 4; ks++) {
                uint32_t af[MT][4];
                uint32_t bf[4][2];
                const uint32_t cA = (uint32_t)(((2 * ks + hAu) ^ xor7) << 4);
                const uint32_t cB = (uint32_t)(((2 * ks + hBu) ^ xor7) << 4);
                #pragma unroll
                for (int mt = 0; mt < MT; mt++)
                    LDSM_X4(af[mt][0], af[mt][1], af[mt][2], af[mt][3],
                            aRowAddr + mt * (16 * 128) + cA);
                #pragma unroll
                for (int p = 0; p < 2; p++) {
                    uint32_t r0, r1, r2, r3;
                    LDSM_X4(r0, r1, r2, r3, bRowAddr + p * (16 * 128) + cB);
                    bf[2*p][0] = r0; bf[2*p][1] = r1;
                    bf[2*p+1][0] = r2; bf[2*p+1][1] = r3;
                }
                #pragma unroll
                for (int mt = 0; mt < MT; mt++)
                    #pragma unroll
                    for (int nt = 0; nt < 4; nt++)
                        mma_f16(cacc[mt][nt], af[mt], bf[nt]);
            }
            if (lid == 0) MBARRIER_ARRIVE(sbar + st * 16 + 8);
            if (++st == NSTAGE) { st = 0; ph ^= 1; }
        }

        // ---- epilogue ----
        const int g = lid >> 2, t4 = lid & 3;
        float* rs_b = rs + (size_t)b * NN;

        #pragma unroll
        for (int mt = 0; mt < MT; mt++) {
            const int r0 = mBase + mWarp + mt * 16 + g;
            const int r1 = r0 + 8;
            float bias0 = 0.f, bias1 = 0.f;
            if (mode == 0) { bias0 = aux[r0]; bias1 = aux[r1]; }
            float s0 = 0.f, s1 = 0.f;
            #pragma unroll
            for (int nt = 0; nt < 4; nt++) {
                const int col = nBase + nWarp + nt * 8 + t4 * 2;
                float v00 = cacc[mt][nt][0], v01 = cacc[mt][nt][1];
                float v10 = cacc[mt][nt][2], v11 = cacc[mt][nt][3];
                if (mode == 3) {
                    const float bc0 = aux[col], bc1 = aux[col + 1];
                    __half* ob = (__half*)outp + (size_t)b * out_bstride;
                    *(__half2*)&ob[(size_t)r0 * out_rstride + col] =
                        __floats2half2_rn(v00 + bc0, v01 + bc1);
                    *(__half2*)&ob[(size_t)r1 * out_rstride + col] =
                        __floats2half2_rn(v10 + bc0, v11 + bc1);
                } else if (mode == 0) {
                    __nv_bfloat16* ob = (__nv_bfloat16*)outp + (size_t)b * out_bstride;
                    *(__nv_bfloat162*)&ob[(size_t)r0 * out_rstride + col] =
                        __floats2bfloat162_rn(v00 + bias0, v01 + bias0);
                    *(__nv_bfloat162*)&ob[(size_t)r1 * out_rstride + col] =
                        __floats2bfloat162_rn(v10 + bias1, v11 + bias1);
                } else {    // mode 2: scores, raw exp (bf16 has fp32 range)
                    v00 = __expf(v00); v01 = __expf(v01);
                    v10 = __expf(v10); v11 = __expf(v11);
                    s0 += v00 + v01; s1 += v10 + v11;
                    __nv_bfloat16* ob = (__nv_bfloat16*)outp + (size_t)b * out_bstride;
                    *(__nv_bfloat162*)&ob[(size_t)r0 * out_rstride + col] =
                        __floats2bfloat162_rn(v00, v01);
                    *(__nv_bfloat162*)&ob[(size_t)r1 * out_rstride + col] =
                        __floats2bfloat162_rn(v10, v11);
                }
            }
            if (mode == 2) {
                s0 += __shfl_xor_sync(0xFFFFFFFFu, s0, 1);
                s0 += __shfl_xor_sync(0xFFFFFFFFu, s0, 2);
                s1 += __shfl_xor_sync(0xFFFFFFFFu, s1, 1);
                s1 += __shfl_xor_sync(0xFFFFFFFFu, s1, 2);
                if (t4 == 0) {
                    atomicAdd(&rs_b[r0], s0);
                    atomicAdd(&rs_b[r1], s1);
                }
            }
        }
    }
}

// ---------------------------------------------------------------------------
// bf16 AV GEMM, BK=128: out[c][i] = gamma*(sum_j v[c][j]*e[i][j])/rs[i] + x
// Tile 256(c) x 128(i) x 128(j), 2 stages x 96 KB.
// ---------------------------------------------------------------------------
constexpr int AV_A_ST = 256 * 256;                // 64 KB
constexpr int AV_B_ST = 128 * 256;                // 32 KB
constexpr int AV_STG  = AV_A_ST + AV_B_ST;        // 96 KB
constexpr int AV_DSMEM = 2 * AV_STG + 1024;

__global__ __launch_bounds__(544)
void av16_kernel(const __grid_constant__ CUtensorMap tma_v,
                 const __grid_constant__ CUtensorMap tma_e,
                 const float* __restrict__ x,
                 const float* __restrict__ rs,
                 const float* __restrict__ gamma,
                 float* __restrict__ outp)
{
    __shared__ __align__(8) uint64_t s_bar[4];
    extern __shared__ char dsm[];
    const uint32_t dbase = (smem_to_u32(dsm) + 1023) & ~1023u;
    const uint32_t sbar  = smem_to_u32(s_bar);

    const int tid = threadIdx.x, wid = tid >> 5, lid = tid & 31;
    const int mBase = blockIdx.x * 256;     // c
    const int nBase = blockIdx.y * 128;     // i
    const int b     = blockIdx.z;
    const int nchunk = NN / 128;            // 32

    if (tid == 0) {
        #pragma unroll
        for (int s = 0; s < 2; s++) {
            MBARRIER_INIT(sbar + s * 16, 1);
            MBARRIER_INIT(sbar + s * 16 + 8, 16);
        }
    }
    __syncthreads();

    if (tid == 512) {
        int ph = 1, st = 0;
        for (int c = 0; c < nchunk; c++) {
            MBARRIER_WAIT_PARITY(sbar + st * 16 + 8, ph);
            MBARRIER_EXPECT_TX(sbar + st * 16, AV_STG);
            const uint32_t SB = dbase + st * AV_STG;
            TMA_LOAD_3D(SB,                   &tma_v, c * 128,      mBase, b, sbar + st * 16);
            TMA_LOAD_3D(SB + 32768,           &tma_v, c * 128 + 64, mBase, b, sbar + st * 16);
            TMA_LOAD_3D(SB + AV_A_ST,         &tma_e, c * 128,      nBase, b, sbar + st * 16);
            TMA_LOAD_3D(SB + AV_A_ST + 16384, &tma_e, c * 128 + 64, nBase, b, sbar + st * 16);
            if (++st == 2) { st = 0; ph ^= 1; }
        }
    }

    if (wid < 16) {
        const int wm = wid & 3, wn = wid >> 2;
        const int mWarp = wm * 64, nWarp = wn * 32;
        const int laneA = lid & 15;
        const int hAu   = (lid >> 4) & 1;
        const int laneB = (lid & 7) + ((lid & 16) ? 8 : 0);
        const int hBu   = (lid >> 3) & 1;
        const int xor7  = lid & 7;

        float cacc[4][4][4] = {};

        int ph = 0, st = 0;
        for (int c = 0; c < nchunk; c++) {
            MBARRIER_WAIT_PARITY(sbar + st * 16, ph);
            const uint32_t Ab = dbase + st * AV_STG;
            const uint32_t Bb = Ab + AV_A_ST;
            const uint32_t aRowAddr = Ab + (mWarp + laneA) * 128;
            const uint32_t bRowAddr = Bb + (nWarp + laneB) * 128;

            #pragma unroll
            for (int kt = 0; kt < 2; kt++) {
                #pragma unroll
                for (int ks = 0; ks < 4; ks++) {
                    uint32_t af[4][4];
                    uint32_t bf[4][2];
                    const uint32_t cA = (uint32_t)(((2 * ks + hAu) ^ xor7) << 4);
                    const uint32_t cB = (uint32_t)(((2 * ks + hBu) ^ xor7) << 4);
                    #pragma unroll
                    for (int mt = 0; mt < 4; mt++)
                        LDSM_X4(af[mt][0], af[mt][1], af[mt][2], af[mt][3],
                                aRowAddr + kt * 32768 + mt * (16 * 128) + cA);
                    #pragma unroll
                    for (int p = 0; p < 2; p++) {
                        uint32_t r0, r1, r2, r3;
                        LDSM_X4(r0, r1, r2, r3, bRowAddr + kt * 16384 + p * (16 * 128) + cB);
                        bf[2*p][0] = r0; bf[2*p][1] = r1;
                        bf[2*p+1][0] = r2; bf[2*p+1][1] = r3;
                    }
                    #pragma unroll
                    for (int mt = 0; mt < 4; mt++)
                        #pragma unroll
                        for (int nt = 0; nt < 4; nt++)
                            mma_bf16(cacc[mt][nt], af[mt], bf[nt]);
                }
            }
            if (lid == 0) MBARRIER_ARRIVE(sbar + st * 16 + 8);
            if (++st == 2) { st = 0; ph ^= 1; }
        }

        const int g = lid >> 2, t4 = lid & 3;
        const float gm = gamma[0];
        const float* rs_b = rs + (size_t)b * NN;
        const float* xb = x + (size_t)b * CC * NN;
        float* ob = outp + (size_t)b * CC * NN;

        #pragma unroll
        for (int mt = 0; mt < 4; mt++) {
            const int r0 = mBase + mWarp + mt * 16 + g;
            const int r1 = r0 + 8;
            #pragma unroll
            for (int nt = 0; nt < 4; nt++) {
                const int col = nBase + nWarp + nt * 8 + t4 * 2;
                const float i0 = __fdividef(1.0f, rs_b[col]);
                const float i1 = __fdividef(1.0f, rs_b[col + 1]);
                const float2 x0 = *(const float2*)&xb[(size_t)r0 * NN + col];
                const float2 x1 = *(const float2*)&xb[(size_t)r1 * NN + col];
                *(float2*)&ob[(size_t)r0 * NN + col] =
                    make_float2(gm * cacc[mt][nt][0] * i0 + x0.x,
                                gm * cacc[mt][nt][1] * i1 + x0.y);
                *(float2*)&ob[(size_t)r1 * NN + col] =
                    make_float2(gm * cacc[mt][nt][2] * i0 + x1.x,
                                gm * cacc[mt][nt][3] * i1 + x1.y);
            }
        }
    }
}

// ---------------------------------------------------------------------------
// Host side
// ---------------------------------------------------------------------------
typedef CUresult (*EncodeFn)(CUtensorMap*, CUtensorMapDataType, cuuint32_t, void*,
                             const cuuint64_t*, const cuuint64_t*, const cuuint32_t*,
                             const cuuint32_t*, CUtensorMapInterleave, CUtensorMapSwizzle,
                             CUtensorMapL2promotion, CUtensorMapFloatOOBfill);

static void build_tm(EncodeFn enc, CUtensorMap* tm, void* ptr,
                     uint64_t d0, uint64_t d1, uint64_t d2,
                     uint64_t s1b, uint64_t s2b, uint32_t b0, uint32_t b1)
{
    cuuint64_t dims[3] = {d0, d1, d2};
    cuuint64_t str[2]  = {s1b, s2b};
    cuuint32_t box[3]  = {b0, b1, 1};
    cuuint32_t es[3]   = {1, 1, 1};
    enc(tm, CU_TENSOR_MAP_DATA_TYPE_UINT16, 3, ptr, dims, str, box, es,
        CU_TENSOR_MAP_INTERLEAVE_NONE, CU_TENSOR_MAP_SWIZZLE_128B,
        CU_TENSOR_MAP_L2_PROMOTION_L2_128B, CU_TENSOR_MAP_FLOAT_OOB_FILL_NONE);
}

extern "C" void kernel_launch(void* const* d_in, const int* in_sizes, int n_in,
                              void* d_out, int out_size)
{
    (void)in_sizes; (void)n_in; (void)out_size;
    const float* x     = (const float*)d_in[0];
    const float* Wq    = (const float*)d_in[1];
    const float* bq    = (const float*)d_in[2];
    const float* Wk    = (const float*)d_in[3];
    const float* bk    = (const float*)d_in[4];
    const float* Wv    = (const float*)d_in[5];
    const float* bv    = (const float*)d_in[6];
    const float* gamma = (const float*)d_in[7];
    float* out = (float*)d_out;

    EncodeFn enc = nullptr;
    cudaDriverEntryPointQueryResult qr;
    cudaGetDriverEntryPointByVersion("cuTensorMapEncodeTiled", (void**)&enc, 12000,
                                     cudaEnableDefault, &qr);

    void *pqk, *pvb, *peb, *pxT, *pwr, *pwqk, *pbqk, *prs;
    cudaGetSymbolAddress(&pqk,  g_qkh);
    cudaGetSymbolAddress(&pvb,  g_vb);
    cudaGetSymbolAddress(&peb,  g_eb);
    cudaGetSymbolAddress(&pxT,  g_xTh);
    cudaGetSymbolAddress(&pwr,  g_wrh);
    cudaGetSymbolAddress(&pwqk, g_wqkh);
    cudaGetSymbolAddress(&pbqk, g_bqk);
    cudaGetSymbolAddress(&prs,  g_rs);

    CUtensorMap tmXT_A64, tmXT_B, tmWQK, tmWV, tmQKa, tmQKb, tmVb256, tmEb128;
    build_tm(enc, &tmXT_A64, pxT, CC, NN, BB, (uint64_t)CC * 2, (uint64_t)NN * CC * 2, 64, 64);
    build_tm(enc, &tmXT_B,   pxT, CC, NN, BB, (uint64_t)CC * 2, (uint64_t)NN * CC * 2, 64, 128);
    build_tm(enc, &tmWQK, pwqk, CC, QK, 1, (uint64_t)CC * 2, (uint64_t)QK * CC * 2, 64, 128);
    build_tm(enc, &tmWV,  pwr,  CC, CC, 1, (uint64_t)CC * 2, (uint64_t)CC * CC * 2, 64, 256);
    build_tm(enc, &tmQKa, pqk, QK, NN, BB, (uint64_t)QK * 2, (uint64_t)NN * QK * 2, 64, 256);
    build_tm(enc, &tmQKb, pqk, QK, NN, BB, (uint64_t)QK * 2, (uint64_t)NN * QK * 2, 64, 128);
    build_tm(enc, &tmVb256, pvb, NN, CC, BB, (uint64_t)NN * 2, (uint64_t)CC * NN * 2, 64, 256);
    build_tm(enc, &tmEb128, peb, NN, NN, BB, (uint64_t)NN * 2, (uint64_t)NN * NN * 2, 64, 128);

    constexpr int DS1 = NSTAGE * (64 * 128 + B16_BY) + 1024;    // MT=1
    constexpr int DS4 = NSTAGE * (256 * 128 + B16_BY) + 1024;   // MT=4
    cudaFuncSetAttribute(gemm16_kernel<1>, cudaFuncAttributeMaxDynamicSharedMemorySize, DS1);
    cudaFuncSetAttribute(gemm16_kernel<4>, cudaFuncAttributeMaxDynamicSharedMemorySize, DS4);
    cudaFuncSetAttribute(av16_kernel, cudaFuncAttributeMaxDynamicSharedMemorySize, AV_DSMEM);

    float* frs = (float*)prs;

    // 1. prep
    xT_half_kernel<<<dim3(NN / 32, CC / 32, BB), 256>>>(x);
    prep_kernel<<<(CC * CC) / 256, 256>>>(Wv, Wq, bq, Wk, bk);
    // 2. qk projection (MT=1, BM=64): 128 CTAs, K=512, fp16 out
    gemm16_kernel<1><<<dim3(QK / BN, NN / 64, BB), 544, DS1>>>(
        tmXT_A64, tmWQK, CC, 3, 1, 0, 0, 0, (const float*)pbqk, frs,
        pqk, (size_t)NN * QK, QK);
    // 3. v projection (MT=4): g_vb[c][n] = bf16(wr·xT^T + bv[c]), K=512
    gemm16_kernel<4><<<dim3(NN / BN, CC / 256, BB), 544, DS4>>>(
        tmWV, tmXT_B, CC, 0, 0, 1, 0, 0, bv, frs,
        pvb, (size_t)CC * NN, NN);
    // 4. scores (MT=4): g_eb[i][j] = bf16(exp(q·k)), fp32 rowsums — NO max pass
    gemm16_kernel<4><<<dim3(NN / BN, NN / 256, BB), 544, DS4>>>(
        tmQKa, tmQKb, DD, 2, 1, 1, 0, DD, nullptr, frs,
        peb, (size_t)NN * NN, NN);
    // 5. AV (bf16, BK=128): out = gamma*(v·e^T)/rs + x, K=4096
    av16_kernel<<<dim3(CC / 256, NN / 128, BB), 544, AV_DSMEM>>>(
        tmVb256, tmEb128, x, frs, gamma, out);
}